// round 6
// baseline (speedup 1.0000x reference)
#include <cuda_runtime.h>

// TransD forward, simplified (eye is identity, RD==ED):
//   h_out = renorm(rp) * <renorm(hp), renorm(hv)> + renorm(hv)
//   rv_out = renorm(rv)
//   t_out = renorm(rp) * <renorm(tp), renorm(tv)> + renorm(tv)
//
// One warp per sample, lane owns one float4.
// 8-value multiplexed shfl reduction; rscale computed on distributed lanes
// (2 MUFU chains instead of 6) before broadcast.

#define NB 8192
#define DV 32u  // float4s per 128-float row
#define FULL 0xffffffffu

__device__ __forceinline__ float dot4(float4 a, float4 b) {
    return a.x * b.x + a.y * b.y + a.z * b.z + a.w * b.w;
}

__device__ __forceinline__ float rscale(float sumsq) {
    float n = sqrtf(sumsq);
    return (n > 1.0f) ? (1.0f / (n + 1e-7f)) : 1.0f;
}

__device__ __forceinline__ void st_cs(float4* p, float4 v) {
    asm volatile("st.global.cs.v4.f32 [%0], {%1,%2,%3,%4};"
                 :: "l"(p), "f"(v.x), "f"(v.y), "f"(v.z), "f"(v.w) : "memory");
}

__global__ __launch_bounds__(128) void transd_kernel(
    const float4* __restrict__ ee,   // entity_emb      [ENT*32]
    const float4* __restrict__ eep,  // entity_emb_p    [ENT*32]
    const float4* __restrict__ re,   // relation_emb    [REL*32]
    const float4* __restrict__ rep,  // relation_emb_p  [REL*32]
    const int* __restrict__ h,
    const int* __restrict__ r,
    const int* __restrict__ t,
    float4* __restrict__ out)        // [3 * NB * 32]
{
    int gwarp = (blockIdx.x * blockDim.x + threadIdx.x) >> 5;
    unsigned lane = threadIdx.x & 31u;
    if (gwarp >= NB) return;

    int hi = __ldg(&h[gwarp]);
    int ri = __ldg(&r[gwarp]);
    int ti = __ldg(&t[gwarp]);

    // 32-bit element offsets (max 500000*32 < 2^24*... fits easily)
    unsigned oh = (unsigned)hi * DV + lane;
    unsigned ot = (unsigned)ti * DV + lane;
    unsigned orr = (unsigned)ri * DV + lane;

    // all 6 gathers issued up front (max MLP)
    float4 hv = __ldg(ee  + oh);
    float4 hp = __ldg(eep + oh);
    float4 tv = __ldg(ee  + ot);
    float4 tp = __ldg(eep + ot);
    float4 rv = __ldg(re  + orr);
    float4 rp = __ldg(rep + orr);

    // per-lane partials for the 8 reductions
    float p0 = dot4(hv, hv);
    float p1 = dot4(hp, hp);
    float p2 = dot4(tv, tv);
    float p3 = dot4(tp, tp);
    float p4 = dot4(rv, rv);
    float p5 = dot4(rp, rp);
    float p6 = dot4(hp, hv);
    float p7 = dot4(tp, tv);

    // Stage A: reduce each value within groups of 4 lanes (xor 1, 2)
    p0 += __shfl_xor_sync(FULL, p0, 1); p0 += __shfl_xor_sync(FULL, p0, 2);
    p1 += __shfl_xor_sync(FULL, p1, 1); p1 += __shfl_xor_sync(FULL, p1, 2);
    p2 += __shfl_xor_sync(FULL, p2, 1); p2 += __shfl_xor_sync(FULL, p2, 2);
    p3 += __shfl_xor_sync(FULL, p3, 1); p3 += __shfl_xor_sync(FULL, p3, 2);
    p4 += __shfl_xor_sync(FULL, p4, 1); p4 += __shfl_xor_sync(FULL, p4, 2);
    p5 += __shfl_xor_sync(FULL, p5, 1); p5 += __shfl_xor_sync(FULL, p5, 2);
    p6 += __shfl_xor_sync(FULL, p6, 1); p6 += __shfl_xor_sync(FULL, p6, 2);
    p7 += __shfl_xor_sync(FULL, p7, 1); p7 += __shfl_xor_sync(FULL, p7, 2);

    // Stage B: lane (l&3) carries value q (w1) and value 4+q (w2) thru xor 4,8,16
    unsigned q = lane & 3u;
    float w1 = (q & 2u) ? ((q & 1u) ? p3 : p2) : ((q & 1u) ? p1 : p0);
    float w2 = (q & 2u) ? ((q & 1u) ? p7 : p6) : ((q & 1u) ? p5 : p4);
    w1 += __shfl_xor_sync(FULL, w1, 4);
    w2 += __shfl_xor_sync(FULL, w2, 4);
    w1 += __shfl_xor_sync(FULL, w1, 8);
    w2 += __shfl_xor_sync(FULL, w2, 8);
    w1 += __shfl_xor_sync(FULL, w1, 16);
    w2 += __shfl_xor_sync(FULL, w2, 16);
    // lane with (lane&3)==q now holds: w1 = total_q, w2 = total_{4+q}
    // totals: 0:|hv|² 1:|hp|² 2:|tv|² 3:|tp|² 4:|rv|² 5:|rp|² 6:<hp,hv> 7:<tp,tv>

    // rscale on distributed lanes: only 2 MUFU chains per lane
    float r1 = rscale(w1);   // q=0:c_hv  1:c_hp  2:c_tv  3:c_tp
    float r2 = rscale(w2);   // q=0:c_rv  1:c_rp  (q=2,3 garbage-scaled dots, unused)

    float c_hv = __shfl_sync(FULL, r1, 0);
    float c_hp = __shfl_sync(FULL, r1, 1);
    float c_tv = __shfl_sync(FULL, r1, 2);
    float c_tp = __shfl_sync(FULL, r1, 3);
    float c_rv = __shfl_sync(FULL, r2, 0);
    float c_rp = __shfl_sync(FULL, r2, 1);
    float d_h  = __shfl_sync(FULL, w2, 2);
    float d_t  = __shfl_sync(FULL, w2, 3);

    float a_h = c_rp * (d_h * c_hp * c_hv);
    float a_t = c_rp * (d_t * c_tp * c_tv);

    unsigned base = (unsigned)gwarp * DV + lane;

    float4 o;
    o.x = rp.x * a_h + hv.x * c_hv;
    o.y = rp.y * a_h + hv.y * c_hv;
    o.z = rp.z * a_h + hv.z * c_hv;
    o.w = rp.w * a_h + hv.w * c_hv;
    st_cs(&out[base], o);

    o.x = rv.x * c_rv; o.y = rv.y * c_rv; o.z = rv.z * c_rv; o.w = rv.w * c_rv;
    st_cs(&out[NB * DV + base], o);

    o.x = rp.x * a_t + tv.x * c_tv;
    o.y = rp.y * a_t + tv.y * c_tv;
    o.z = rp.z * a_t + tv.z * c_tv;
    o.w = rp.w * a_t + tv.w * c_tv;
    st_cs(&out[2u * NB * DV + base], o);
}

extern "C" void kernel_launch(void* const* d_in, const int* in_sizes, int n_in,
                              void* d_out, int out_size) {
    const float4* ee  = (const float4*)d_in[0];
    const float4* eep = (const float4*)d_in[1];
    const float4* re  = (const float4*)d_in[2];
    const float4* rep = (const float4*)d_in[3];
    const int* h = (const int*)d_in[4];
    const int* r = (const int*)d_in[5];
    const int* t = (const int*)d_in[6];

    // 4 warps (128 threads) per block, 1 sample per warp -> 2048 blocks
    int blocks = (NB * 32 + 127) / 128;
    transd_kernel<<<blocks, 128>>>(ee, eep, re, rep, h, r, t, (float4*)d_out);
}